// round 2
// baseline (speedup 1.0000x reference)
#include <cuda_runtime.h>

// Problem constants
#define N_ROWS   65536      // 16*1024*4 rows of CODE_DIM
#define DIMV     128        // CODE_DIM floats per row
#define KCODES   1024       // NUM_EMBEDDINGS
#define CHUNK    64         // codes per smem tile
#define TPB      128        // threads per block (1 row per thread)
#define NBLOCKS  (N_ROWS / TPB)   // 512

// Scratch (device globals: no allocation allowed)
__device__ float  g_re[KCODES];     // ||e_k||^2 in fp32 (reference rounding class)
__device__ int    g_counts[KCODES];
__device__ double g_loss;

// Packed dual-FMA: d.lo += a.lo*b.lo ; d.hi += a.hi*b.hi  (ptxas never emits this from C++)
static __device__ __forceinline__ void ffma2(unsigned long long &d,
                                             unsigned long long a,
                                             unsigned long long b) {
    asm("fma.rn.f32x2 %0, %1, %2, %0;" : "+l"(d) : "l"(a), "l"(b));
}

union U2 { unsigned long long u; float2 f; };

// ---------------------------------------------------------------------------
// Kernel 1: per-code ||e||^2 (fp32 squares, fp64 sum, round to fp32),
//           zero histogram + loss accumulator
// ---------------------------------------------------------------------------
__global__ void vq_init(const float* __restrict__ emb) {
    int k = blockIdx.x * blockDim.x + threadIdx.x;
    if (k < KCODES) {
        const float4* e4 = (const float4*)(emb + (size_t)k * DIMV);
        double s = 0.0;
#pragma unroll
        for (int i = 0; i < DIMV / 4; ++i) {
            float4 v = e4[i];
            s += (double)__fmul_rn(v.x, v.x) + (double)__fmul_rn(v.y, v.y)
               + (double)__fmul_rn(v.z, v.z) + (double)__fmul_rn(v.w, v.w);
        }
        g_re[k]     = (float)s;
        g_counts[k] = 0;
    }
    if (k == 0) g_loss = 0.0;
}

// ---------------------------------------------------------------------------
// Kernel 2: argmin over codes + fused gather/output/loss/histogram
// One thread == one row (x row lives entirely in registers as f32x2 pairs).
// Distance replicates the reference's fp32 rounding association:
//   d_k = fadd_rn( fadd_rn(rx, re_k), -2 * (x . e_k) )
// ---------------------------------------------------------------------------
__global__ __launch_bounds__(TPB, 2)
void vq_main(const float* __restrict__ x, const float* __restrict__ emb,
             float* __restrict__ out) {
    __shared__ __align__(16) float sE[CHUNK * DIMV];   // 32 KB codebook tile
    __shared__ float  sRE[KCODES];                     // 4 KB ||e||^2
    __shared__ int    sBest[TPB];
    __shared__ double sLoss[TPB / 32];

    const int tid = threadIdx.x;
    const size_t row = (size_t)blockIdx.x * TPB + tid;

    // cache code norms (broadcast-read later)
    for (int i = tid; i < KCODES; i += TPB) sRE[i] = g_re[i];

    // load my row into registers: 128 floats = 64 packed f32x2
    unsigned long long xr[DIMV / 2];
    {
        const ulonglong2* xp = (const ulonglong2*)(x + row * DIMV);
#pragma unroll
        for (int i = 0; i < DIMV / 4; ++i) {
            ulonglong2 v = xp[i];
            xr[2 * i] = v.x;
            xr[2 * i + 1] = v.y;
        }
    }

    // rx = ||x||^2 : fp32 squares, fp64 accumulate, round to fp32.
    // (Exact value is argmin-invariant within a binade; fp64 keeps us safely
    //  within ~0.1 ulp of any summation order the reference used.)
    float rx;
    {
        double s = 0.0;
#pragma unroll
        for (int i = 0; i < DIMV / 2; ++i) {
            U2 u; u.u = xr[i];
            s += (double)__fmul_rn(u.f.x, u.f.x) + (double)__fmul_rn(u.f.y, u.f.y);
        }
        rx = (float)s;
    }

    float best = 3.402823466e38f;
    int   bi   = 0;

    for (int cb = 0; cb < KCODES; cb += CHUNK) {
        __syncthreads();
        // stage codebook chunk (row-major, same layout as global) into smem
        {
            const float4* g  = (const float4*)(emb + (size_t)cb * DIMV);
            float4*       s4 = (float4*)sE;
            for (int i = tid; i < CHUNK * DIMV / 4; i += TPB) s4[i] = g[i];
        }
        __syncthreads();

#pragma unroll 1
        for (int c = 0; c < CHUNK; ++c) {
            const ulonglong2* ep = (const ulonglong2*)(sE + c * DIMV);
            unsigned long long a0 = 0ull, a1 = 0ull, a2 = 0ull, a3 = 0ull;
#pragma unroll
            for (int b = 0; b < 8; ++b) {
                // batch 4 LDS.128 (all-lane broadcast), then 8 packed FMAs
                ulonglong2 e0 = ep[4 * b + 0];
                ulonglong2 e1 = ep[4 * b + 1];
                ulonglong2 e2 = ep[4 * b + 2];
                ulonglong2 e3 = ep[4 * b + 3];
                ffma2(a0, xr[8 * b + 0], e0.x);
                ffma2(a1, xr[8 * b + 1], e0.y);
                ffma2(a2, xr[8 * b + 2], e1.x);
                ffma2(a3, xr[8 * b + 3], e1.y);
                ffma2(a0, xr[8 * b + 4], e2.x);
                ffma2(a1, xr[8 * b + 5], e2.y);
                ffma2(a2, xr[8 * b + 6], e3.x);
                ffma2(a3, xr[8 * b + 7], e3.y);
            }
            U2 u0, u1, u2, u3;
            u0.u = a0; u1.u = a1; u2.u = a2; u3.u = a3;
            float m = ((u0.f.x + u0.f.y) + (u1.f.x + u1.f.y))
                    + ((u2.f.x + u2.f.y) + (u3.f.x + u3.f.y));
            // Reference association: (rx + re_k) - 2*m, each add rounded fp32,
            // no FMA contraction.
            float d = __fadd_rn(__fadd_rn(rx, sRE[cb + c]), __fmul_rn(m, -2.0f));
            // jnp.argmin keeps the lowest index on ties -> strict '<'.
            if (d < best) { best = d; bi = cb + c; }
        }
    }

    sBest[tid] = bi;
    atomicAdd(&g_counts[bi], 1);
    __syncthreads();

    // fused output: quantized_ste == gathered codebook row; loss partial
    double ls = 0.0;
    {
        const float4* xin4 = (const float4*)(x + (size_t)blockIdx.x * TPB * DIMV);
        float4*       o4   = (float4*)(out + (size_t)blockIdx.x * TPB * DIMV);
        const float4* e4   = (const float4*)emb;
        for (int i = tid; i < TPB * DIMV / 4; i += TPB) {
            int r   = i >> 5;          // DIMV/4 = 32 float4 per row
            int col = i & 31;
            float4 q  = e4[(size_t)sBest[r] * 32 + col];
            float4 xv = xin4[i];
            o4[i] = q;
            double dx = (double)q.x - xv.x, dy = (double)q.y - xv.y;
            double dz = (double)q.z - xv.z, dw = (double)q.w - xv.w;
            ls += dx * dx + dy * dy + dz * dz + dw * dw;
        }
    }
#pragma unroll
    for (int o = 16; o > 0; o >>= 1) ls += __shfl_down_sync(0xffffffffu, ls, o);
    if ((tid & 31) == 0) sLoss[tid >> 5] = ls;
    __syncthreads();
    if (tid == 0) {
        double t = 0.0;
#pragma unroll
        for (int i = 0; i < TPB / 32; ++i) t += sLoss[i];
        atomicAdd(&g_loss, t);
    }
}

// ---------------------------------------------------------------------------
// Kernel 3: perplexity + loss scalars
// ---------------------------------------------------------------------------
__global__ void vq_finalize(float* __restrict__ out, int out_size) {
    __shared__ float red[8];
    int tid = threadIdx.x;  // 256
    float acc = 0.f;
    for (int k = tid; k < KCODES; k += 256) {
        float p = (float)g_counts[k] * (1.0f / (float)N_ROWS);
        acc += p * logf(p + 1e-10f);
    }
#pragma unroll
    for (int o = 16; o > 0; o >>= 1) acc += __shfl_down_sync(0xffffffffu, acc, o);
    if ((tid & 31) == 0) red[tid >> 5] = acc;
    __syncthreads();
    if (tid == 0) {
        float s = 0.f;
#pragma unroll
        for (int i = 0; i < 8; ++i) s += red[i];
        out[out_size - 2] = (float)(1.25 * (g_loss / (double)(N_ROWS * DIMV)));
        out[out_size - 1] = expf(-s);
    }
}

// ---------------------------------------------------------------------------
extern "C" void kernel_launch(void* const* d_in, const int* in_sizes, int n_in,
                              void* d_out, int out_size) {
    const float* x   = (const float*)d_in[0];   // inputs [16,1024,512] fp32
    const float* emb = (const float*)d_in[1];   // emb_weight [1024,128] fp32
    float*       out = (float*)d_out;
    (void)in_sizes; (void)n_in;

    vq_init<<<(KCODES + 255) / 256, 256>>>(emb);
    vq_main<<<NBLOCKS, TPB>>>(x, emb, out);
    vq_finalize<<<1, 256>>>(out, out_size);
}

// round 4
// speedup vs baseline: 1.0322x; 1.0322x over previous
#include <cuda_runtime.h>
#include <cstdint>

// Problem constants
#define N_ROWS   65536
#define DIMV     128
#define KCODES   1024
#define RPB      128                 // rows per block
#define CPC      64                  // codes per chunk
#define TPB      256
#define NBLOCKS  (N_ROWS / RPB)      // 512
#define NCHUNK   (KCODES / CPC)      // 16

// smem layout strides (padded against bank conflicts; ALL 16B multiples)
#define XS_STRIDE 1040               // per-k2 plane: 128 rows * 8B + 16B pad
#define ES_STRIDE 528                // per-code row: 512B + 16B pad
#define XS_BYTES  (64 * XS_STRIDE)   // 66560
#define ES_BYTES  (CPC * ES_STRIDE)  // 33792
#define SM_RE_OFF   (XS_BYTES + 2 * ES_BYTES)          // 134144
#define SM_RX_OFF   (SM_RE_OFF + KCODES * 4)           // 138240
#define SM_REDD_OFF (SM_RX_OFF + RPB * 4)              // 138752
#define SM_REDI_OFF (SM_REDD_OFF + RPB * 8 * 4)        // 142848
#define SM_BEST_OFF (SM_REDI_OFF + RPB * 8 * 4)        // 146944
#define SM_LOSS_OFF (SM_BEST_OFF + RPB * 4)            // 147456
#define SMEM_TOTAL  (SM_LOSS_OFF + 8 * 8)              // 147520

// Scratch (device globals: no allocation allowed)
__device__ float  g_re[KCODES];
__device__ int    g_counts[KCODES];
__device__ double g_loss;

typedef unsigned long long ull;
union U2 { ull u; float2 f; };

// Packed dual-FMA (PTX-only; ptxas never auto-fuses)
static __device__ __forceinline__ void ffma2(ull &d, ull a, ull b) {
    asm("fma.rn.f32x2 %0, %1, %2, %0;" : "+l"(d) : "l"(a), "l"(b));
}

static __device__ __forceinline__ void cp_async16(uint32_t dst, const void* src) {
    asm volatile("cp.async.cg.shared.global [%0], [%1], 16;\n" :: "r"(dst), "l"(src));
}
#define CP_COMMIT() asm volatile("cp.async.commit_group;\n" ::: "memory")
#define CP_WAIT1()  asm volatile("cp.async.wait_group 1;\n" ::: "memory")
#define CP_WAIT0()  asm volatile("cp.async.wait_group 0;\n" ::: "memory")

// ---------------------------------------------------------------------------
// Kernel 1: per-code ||e||^2 (fp32 squares, fp64 sum -> fp32), zero scratch
// ---------------------------------------------------------------------------
__global__ void vq_init(const float* __restrict__ emb) {
    int k = blockIdx.x * blockDim.x + threadIdx.x;
    if (k < KCODES) {
        const float4* e4 = (const float4*)(emb + (size_t)k * DIMV);
        double s = 0.0;
#pragma unroll
        for (int i = 0; i < DIMV / 4; ++i) {
            float4 v = e4[i];
            s += (double)__fmul_rn(v.x, v.x) + (double)__fmul_rn(v.y, v.y)
               + (double)__fmul_rn(v.z, v.z) + (double)__fmul_rn(v.w, v.w);
        }
        g_re[k]     = (float)s;
        g_counts[k] = 0;
    }
    if (k == 0) g_loss = 0.0;
}

// ---------------------------------------------------------------------------
// Kernel 2: register-blocked distance GEMM + argmin + fused outputs
// Block: 128 rows x all codes (64-code chunks). Thread tile: 4 rows x 8 codes.
// ---------------------------------------------------------------------------
__global__ __launch_bounds__(TPB, 1)
void vq_main(const float* __restrict__ x, const float* __restrict__ emb,
             float* __restrict__ out) {
    extern __shared__ __align__(16) char sm[];
    char*   xs    = sm;                             // transposed x tile
    char*   esbuf[2] = { sm + XS_BYTES, sm + XS_BYTES + ES_BYTES };
    float*  sRE   = (float*)(sm + SM_RE_OFF);
    float*  sRX   = (float*)(sm + SM_RX_OFF);
    float*  sRedD = (float*)(sm + SM_REDD_OFF);
    int*    sRedI = (int*)  (sm + SM_REDI_OFF);
    int*    sBest = (int*)  (sm + SM_BEST_OFF);
    double* sLoss = (double*)(sm + SM_LOSS_OFF);

    const int tid = threadIdx.x;
    const int cg  = tid & 7;          // code group (8 strided codes)
    const int rg  = tid >> 3;         // row group (4 consecutive rows)
    const size_t row0 = (size_t)blockIdx.x * RPB;

    // ---- prefetch e-chunk 0 (cp.async, double-buffered) ----
    {
        const char* src = (const char*)(emb);   // chunk 0 starts at code 0
        uint32_t dst = (uint32_t)__cvta_generic_to_shared(esbuf[0]);
#pragma unroll
        for (int q = 0; q < 8; ++q) {
            int flat = q * TPB + tid;           // 0..2047 16B units
            int code = flat >> 5;               // 32 x 16B per code
            int off  = (flat & 31) * 16;
            cp_async16(dst + code * ES_STRIDE + off, src + code * 512 + off);
        }
        CP_COMMIT();
    }

    // ---- cache code norms ----
    for (int i = tid; i < KCODES; i += TPB) sRE[i] = g_re[i];

    // ---- load + transpose x tile: xs[k2-plane][row] (8B packed pairs) ----
    {
        const float4* xg = (const float4*)(x + row0 * DIMV);
#pragma unroll
        for (int it = 0; it < 16; ++it) {
            int flat = it * TPB + tid;          // 0..4095 float4s
            int seg  = flat >> 3;               // 128B segment
            int j    = flat & 7;
            int row  = seg >> 2;                // 4 segments per row
            int k4   = (seg & 3) * 8 + j;       // float4 index within row
            float4 v = xg[row * 32 + k4];
            int k2 = 2 * k4;
            *(float2*)(xs + (size_t)k2 * XS_STRIDE + row * 8)       = make_float2(v.x, v.y);
            *(float2*)(xs + (size_t)(k2 + 1) * XS_STRIDE + row * 8) = make_float2(v.z, v.w);
        }
    }
    __syncthreads();

    // ---- row norms rx (fp32 squares, fp64 sum -> fp32), from transposed tile ----
    if (tid < RPB) {
        double s0 = 0.0, s1 = 0.0;
#pragma unroll 8
        for (int k2 = 0; k2 < 64; ++k2) {
            float2 p = *(const float2*)(xs + (size_t)k2 * XS_STRIDE + tid * 8);
            s0 += (double)__fmul_rn(p.x, p.x);
            s1 += (double)__fmul_rn(p.y, p.y);
        }
        sRX[tid] = (float)(s0 + s1);
    }
    __syncthreads();

    float rxr[4];
#pragma unroll
    for (int r = 0; r < 4; ++r) rxr[r] = sRX[rg * 4 + r];

    float bestD[4] = { 3.402823466e38f, 3.402823466e38f, 3.402823466e38f, 3.402823466e38f };
    int   bestI[4] = { 0, 0, 0, 0 };

    // ---- main loop over 16 code chunks ----
    for (int cb = 0; cb < NCHUNK; ++cb) {
        const int buf = cb & 1;
        // prefetch next chunk into the other buffer
        if (cb + 1 < NCHUNK) {
            const char* src = (const char*)(emb + (size_t)(cb + 1) * CPC * DIMV);
            uint32_t dst = (uint32_t)__cvta_generic_to_shared(esbuf[buf ^ 1]);
#pragma unroll
            for (int q = 0; q < 8; ++q) {
                int flat = q * TPB + tid;
                int code = flat >> 5;
                int off  = (flat & 31) * 16;
                cp_async16(dst + code * ES_STRIDE + off, src + code * 512 + off);
            }
            CP_COMMIT();
            CP_WAIT1();
        } else {
            CP_WAIT0();
        }
        __syncthreads();   // (A) current buffer fully staged & visible

        const char* eb = esbuf[buf];
        const char* xp = xs + rg * 32;
        // 8 per-thread e-row base pointers: codes c = j*8 + cg (strided -> bank-clean)
        const char* bp[8];
#pragma unroll
        for (int j = 0; j < 8; ++j) bp[j] = eb + (size_t)(j * 8 + cg) * ES_STRIDE;

        ull acc[4][8];
#pragma unroll
        for (int r = 0; r < 4; ++r)
#pragma unroll
            for (int j = 0; j < 8; ++j) acc[r][j] = 0ull;

        // ping-pong register double-buffered k-loop (64 packed k-pairs)
        ull A0[4], B0[8], A1[4], B1[8];
        {
            ulonglong2 t0 = *(const ulonglong2*)(xp);
            ulonglong2 t1 = *(const ulonglong2*)(xp + 16);
            A0[0] = t0.x; A0[1] = t0.y; A0[2] = t1.x; A0[3] = t1.y;
#pragma unroll
            for (int j = 0; j < 8; ++j) B0[j] = *(const ull*)(bp[j]);
        }
#pragma unroll 4
        for (int k2 = 0; k2 < 64; k2 += 2) {
            // prefetch k2+1
            {
                const char* p = xp + (size_t)(k2 + 1) * XS_STRIDE;
                ulonglong2 t0 = *(const ulonglong2*)(p);
                ulonglong2 t1 = *(const ulonglong2*)(p + 16);
                A1[0] = t0.x; A1[1] = t0.y; A1[2] = t1.x; A1[3] = t1.y;
#pragma unroll
                for (int j = 0; j < 8; ++j) B1[j] = *(const ull*)(bp[j] + (k2 + 1) * 8);
            }
#pragma unroll
            for (int r = 0; r < 4; ++r)
#pragma unroll
                for (int j = 0; j < 8; ++j) ffma2(acc[r][j], A0[r], B0[j]);
            // prefetch k2+2
            if (k2 + 2 < 64) {
                const char* p = xp + (size_t)(k2 + 2) * XS_STRIDE;
                ulonglong2 t0 = *(const ulonglong2*)(p);
                ulonglong2 t1 = *(const ulonglong2*)(p + 16);
                A0[0] = t0.x; A0[1] = t0.y; A0[2] = t1.x; A0[3] = t1.y;
#pragma unroll
                for (int j = 0; j < 8; ++j) B0[j] = *(const ull*)(bp[j] + (k2 + 2) * 8);
            }
#pragma unroll
            for (int r = 0; r < 4; ++r)
#pragma unroll
                for (int j = 0; j < 8; ++j) ffma2(acc[r][j], A1[r], B1[j]);
        }

        // per-chunk epilogue: reference-rounded distance + thread-local argmin
#pragma unroll
        for (int r = 0; r < 4; ++r) {
#pragma unroll
            for (int j = 0; j < 8; ++j) {
                U2 u; u.u = acc[r][j];
                float m = __fadd_rn(u.f.x, u.f.y);
                int c = cb * CPC + j * 8 + cg;
                float d = __fadd_rn(__fadd_rn(rxr[r], sRE[c]), __fmul_rn(m, -2.0f));
                if (d < bestD[r]) { bestD[r] = d; bestI[r] = c; }
            }
        }
        __syncthreads();   // (B) done reading es[buf] before next prefetch overwrites it
    }

    // ---- cross-thread argmin reduction (8 code-groups per row) ----
#pragma unroll
    for (int r = 0; r < 4; ++r) {
        sRedD[(rg * 4 + r) * 8 + cg] = bestD[r];
        sRedI[(rg * 4 + r) * 8 + cg] = bestI[r];
    }
    __syncthreads();
    if (tid < RPB) {
        float bd = sRedD[tid * 8];
        int   bi = sRedI[tid * 8];
#pragma unroll
        for (int c = 1; c < 8; ++c) {
            float d  = sRedD[tid * 8 + c];
            int   ii = sRedI[tid * 8 + c];
            if (d < bd || (d == bd && ii < bi)) { bd = d; bi = ii; }
        }
        sBest[tid] = bi;
        atomicAdd(&g_counts[bi], 1);
    }
    __syncthreads();

    // ---- fused output: gather codebook rows, write out, fp64 loss partial ----
    double ls = 0.0;
    {
        const float4* xin4 = (const float4*)(x + row0 * DIMV);
        float4*       o4   = (float4*)(out + row0 * DIMV);
        const float4* e4   = (const float4*)emb;
        for (int i = tid; i < RPB * (DIMV / 4); i += TPB) {
            int r   = i >> 5;              // 32 float4 per row
            int col = i & 31;
            float4 q  = e4[(size_t)sBest[r] * 32 + col];
            float4 xv = xin4[i];
            o4[i] = q;
            double dx = (double)q.x - xv.x, dy = (double)q.y - xv.y;
            double dz = (double)q.z - xv.z, dw = (double)q.w - xv.w;
            ls += dx * dx + dy * dy + dz * dz + dw * dw;
        }
    }
#pragma unroll
    for (int o = 16; o > 0; o >>= 1) ls += __shfl_down_sync(0xffffffffu, ls, o);
    if ((tid & 31) == 0) sLoss[tid >> 5] = ls;
    __syncthreads();
    if (tid == 0) {
        double t = 0.0;
#pragma unroll
        for (int i = 0; i < 8; ++i) t += sLoss[i];
        atomicAdd(&g_loss, t);
    }
}

// ---------------------------------------------------------------------------
// Kernel 3: perplexity + loss scalars
// ---------------------------------------------------------------------------
__global__ void vq_finalize(float* __restrict__ out, int out_size) {
    __shared__ float red[8];
    int tid = threadIdx.x;  // 256
    float acc = 0.f;
    for (int k = tid; k < KCODES; k += 256) {
        float p = (float)g_counts[k] * (1.0f / (float)N_ROWS);
        acc += p * logf(p + 1e-10f);
    }
#pragma unroll
    for (int o = 16; o > 0; o >>= 1) acc += __shfl_down_sync(0xffffffffu, acc, o);
    if ((tid & 31) == 0) red[tid >> 5] = acc;
    __syncthreads();
    if (tid == 0) {
        float s = 0.f;
#pragma unroll
        for (int i = 0; i < 8; ++i) s += red[i];
        out[out_size - 2] = (float)(1.25 * (g_loss / (double)(N_ROWS * DIMV)));
        out[out_size - 1] = expf(-s);
    }
}

// ---------------------------------------------------------------------------
extern "C" void kernel_launch(void* const* d_in, const int* in_sizes, int n_in,
                              void* d_out, int out_size) {
    const float* x   = (const float*)d_in[0];   // inputs [16,1024,512] fp32
    const float* emb = (const float*)d_in[1];   // emb_weight [1024,128] fp32
    float*       out = (float*)d_out;
    (void)in_sizes; (void)n_in;

    cudaFuncSetAttribute(vq_main, cudaFuncAttributeMaxDynamicSharedMemorySize,
                         SMEM_TOTAL);

    vq_init<<<(KCODES + 255) / 256, 256>>>(emb);
    vq_main<<<NBLOCKS, TPB, SMEM_TOTAL>>>(x, emb, out);
    vq_finalize<<<1, 256>>>(out, out_size);
}

// round 7
// speedup vs baseline: 1.2119x; 1.1741x over previous
#include <cuda_runtime.h>
#include <cuda_bf16.h>
#include <cstdint>

// ---------------------------------------------------------------- constants
#define N_ROWS   65536
#define DIMV     128
#define KCODES   1024
#define RPB      128                  // rows per block (M)
#define CPC      64                   // codes per chunk (N)
#define NCH      (KCODES / CPC)       // 16
#define TPB      256
#define NBLOCKS  (N_ROWS / RPB)       // 512

// padded bf16 row: 136 elems = 272 B = 17 x 16B granules (conflict-free ldmatrix)
#define ROWB     272
#define XA_SPLIT (RPB * ROWB)         // 34816
#define B_SPLIT  (CPC * ROWB)         // 17408
#define B_BUF    (3 * B_SPLIT)        // 52224
#define ET_SPLIT (KCODES * ROWB)      // 278528

// smem layout
#define SM_XA    0
#define SM_B     (3 * XA_SPLIT)                   // 104448
#define SM_RE    (SM_B + 2 * B_BUF)               // 208896
#define SM_RX    (SM_RE + KCODES * 4)             // 212992
#define SM_REDD  (SM_RX + RPB * 4)                // 213504  (RPB*2*2 floats)
#define SM_REDI  (SM_REDD + RPB * 4 * 4)          // 215552
#define SM_BEST  (SM_REDI + RPB * 4 * 4)          // 217600
#define SM_LOSS  (SM_BEST + RPB * 4)              // 218112
#define SMEM_TOTAL (SM_LOSS + 8 * 8)              // 218176

// ---------------------------------------------------------------- scratch
__device__ float  g_re[KCODES];
__device__ int    g_counts[KCODES];
__device__ double g_loss;
// padded bf16 codebook splits: [3][1024][136] bf16
__device__ __align__(16) unsigned char g_eTp[3u * ET_SPLIT];

// ---------------------------------------------------------------- helpers
__device__ __forceinline__ uint32_t smem_u32(const void* p) {
    uint32_t a;
    asm("{ .reg .u64 t; cvta.to.shared.u64 t, %1; cvt.u32.u64 %0, t; }"
        : "=r"(a) : "l"(p));
    return a;
}
static __device__ __forceinline__ void cp_async16(uint32_t dst, const void* src) {
    asm volatile("cp.async.cg.shared.global [%0], [%1], 16;\n" :: "r"(dst), "l"(src));
}
#define CP_COMMIT() asm volatile("cp.async.commit_group;\n" ::: "memory")
#define CP_WAIT1()  asm volatile("cp.async.wait_group 1;\n" ::: "memory")

#define LDSM4(r, addr) \
    asm volatile("ldmatrix.sync.aligned.m8n8.x4.shared.b16 {%0,%1,%2,%3}, [%4];" \
        : "=r"((r)[0]), "=r"((r)[1]), "=r"((r)[2]), "=r"((r)[3]) : "r"(addr))

#define MMA16816(c, a, b0, b1) \
    asm volatile("mma.sync.aligned.m16n8k16.row.col.f32.bf16.bf16.f32 " \
        "{%0,%1,%2,%3}, {%4,%5,%6,%7}, {%8,%9}, {%0,%1,%2,%3};" \
        : "+f"((c)[0]), "+f"((c)[1]), "+f"((c)[2]), "+f"((c)[3]) \
        : "r"((a)[0]), "r"((a)[1]), "r"((a)[2]), "r"((a)[3]), "r"(b0), "r"(b1))

// ordering: (dA,iA) < (dB,iB)  [strict, lowest index on ties]
static __device__ __forceinline__ bool lt(float dA, int iA, float dB, int iB) {
    return dA < dB || (dA == dB && iA < iB);
}
// insert candidate into (best, sec) pair
static __device__ __forceinline__ void ins2(float d, int i,
                                            float& bD, int& bI, float& sD, int& sI) {
    if (lt(d, i, bD, bI)) { sD = bD; sI = bI; bD = d; bI = i; }
    else if (lt(d, i, sD, sI)) { sD = d; sI = i; }
}

// bf16 triple-split limb sp of a scalar
static __device__ __forceinline__ __nv_bfloat16 split_bf(float f, int sp) {
    __nv_bfloat16 h1 = __float2bfloat16_rn(f);
    if (sp == 0) return h1;
    float r1 = __fadd_rn(f, -__bfloat162float(h1));
    __nv_bfloat16 h2 = __float2bfloat16_rn(r1);
    if (sp == 1) return h2;
    return __float2bfloat16_rn(__fadd_rn(r1, -__bfloat162float(h2)));
}

// ---------------------------------------------------------------- prep
__global__ void vq_prep(const float* __restrict__ emb) {
    int g = blockIdx.x * blockDim.x + threadIdx.x;   // 0..2047
    int k = g >> 1, half = g & 1;
    const float4* e4 = (const float4*)(emb + (size_t)k * DIMV + half * 64);
    unsigned char* base = g_eTp + (size_t)k * ROWB + half * 128;
    double s = 0.0;
#pragma unroll
    for (int i = 0; i < 16; ++i) {
        float4 v = e4[i];
        s += (double)__fmul_rn(v.x, v.x) + (double)__fmul_rn(v.y, v.y)
           + (double)__fmul_rn(v.z, v.z) + (double)__fmul_rn(v.w, v.w);
#pragma unroll
        for (int sp = 0; sp < 3; ++sp) {
            unsigned char* p = base + (size_t)sp * ET_SPLIT + i * 8;
            *(__nv_bfloat162*)(p)     = __halves2bfloat162(split_bf(v.x, sp), split_bf(v.y, sp));
            *(__nv_bfloat162*)(p + 4) = __halves2bfloat162(split_bf(v.z, sp), split_bf(v.w, sp));
        }
    }
    s += __shfl_xor_sync(0xffffffffu, s, 1);
    if (!half) { g_re[k] = (float)s; g_counts[k] = 0; }
    if (g == 0) g_loss = 0.0;
}

// ---------------------------------------------------------------- main
__global__ __launch_bounds__(TPB, 1)
void vq_main(const float* __restrict__ x, const float* __restrict__ emb,
             float* __restrict__ out) {
    extern __shared__ __align__(16) char sm[];
    float*  sRE   = (float*)(sm + SM_RE);
    float*  sRX   = (float*)(sm + SM_RX);
    float*  sRedD = (float*)(sm + SM_REDD);
    int*    sRedI = (int*)  (sm + SM_REDI);
    int*    sBest = (int*)  (sm + SM_BEST);
    double* sLoss = (double*)(sm + SM_LOSS);

    const uint32_t smb = smem_u32(sm);
    const int tid = threadIdx.x, wid = tid >> 5, l = tid & 31;
    const int wm = wid & 3, wn = wid >> 2;          // 4 x 2 warp grid
    const size_t row0 = (size_t)blockIdx.x * RPB;

    // ---- stage x splits (padded bf16) + fp64 row norms ----
    {
        int row = tid >> 1, half = tid & 1;
        const float4* xr = (const float4*)(x + (row0 + row) * DIMV + half * 64);
        char* base = sm + SM_XA + row * ROWB + half * 128;
        double s = 0.0;
#pragma unroll
        for (int i = 0; i < 16; ++i) {
            float4 v = xr[i];
            s += (double)__fmul_rn(v.x, v.x) + (double)__fmul_rn(v.y, v.y)
               + (double)__fmul_rn(v.z, v.z) + (double)__fmul_rn(v.w, v.w);
#pragma unroll
            for (int sp = 0; sp < 3; ++sp) {
                char* p = base + sp * XA_SPLIT + i * 8;
                *(__nv_bfloat162*)(p)     = __halves2bfloat162(split_bf(v.x, sp), split_bf(v.y, sp));
                *(__nv_bfloat162*)(p + 4) = __halves2bfloat162(split_bf(v.z, sp), split_bf(v.w, sp));
            }
        }
        s += __shfl_xor_sync(0xffffffffu, s, 1);
        if (!half) sRX[row] = (float)s;
    }
    for (int i = tid; i < KCODES; i += TPB) sRE[i] = g_re[i];

    // ---- prefetch B chunks 0,1 ----
    {
        const char* srcb = (const char*)g_eTp;
#pragma unroll
        for (int c = 0; c < 2; ++c) {
            uint32_t dst = smb + SM_B + c * B_BUF;
            const char* src = srcb + (size_t)c * CPC * ROWB;
            for (int i = tid; i < B_BUF / 16; i += TPB) {
                int s = i / (B_SPLIT / 16), r = i - s * (B_SPLIT / 16);
                cp_async16(dst + i * 16, src + (size_t)s * ET_SPLIT + r * 16);
            }
            CP_COMMIT();
        }
    }
    __syncthreads();   // staging of A/rx visible

    float rxv[4];
#pragma unroll
    for (int s = 0; s < 4; ++s) rxv[s] = sRX[wm * 32 + (l >> 2) + s * 8];

    uint32_t aAddr[3][2];
#pragma unroll
    for (int sp = 0; sp < 3; ++sp)
#pragma unroll
        for (int mi = 0; mi < 2; ++mi)
            aAddr[sp][mi] = smb + SM_XA + sp * XA_SPLIT
                          + (wm * 32 + mi * 16 + (l & 15)) * ROWB + ((l >> 4) & 1) * 16;
    uint32_t bOff[3][2];
#pragma unroll
    for (int sp = 0; sp < 3; ++sp)
#pragma unroll
        for (int g = 0; g < 2; ++g)
            bOff[sp][g] = sp * B_SPLIT
                        + (wn * 32 + g * 16 + (l & 7) + ((l >> 4) & 1) * 8) * ROWB
                        + ((l >> 3) & 1) * 16;

    float bestD[4], secD[4];
    int   bestI[4], secI[4];
#pragma unroll
    for (int s = 0; s < 4; ++s) {
        bestD[s] = secD[s] = 3.402823466e38f;
        bestI[s] = secI[s] = 0x7fffffff;
    }

    const int PA[6] = {0, 0, 1, 1, 0, 2}, PB[6] = {0, 1, 0, 1, 2, 0};

#pragma unroll 1
    for (int c = 0; c < NCH; ++c) {
        CP_WAIT1();
        __syncthreads();                 // buf (c&1) ready for all
        uint32_t bB = smb + SM_B + (c & 1) * B_BUF;

        float acc[2][4][4];
#pragma unroll
        for (int mi = 0; mi < 2; ++mi)
#pragma unroll
            for (int ni = 0; ni < 4; ++ni)
#pragma unroll
                for (int q = 0; q < 4; ++q) acc[mi][ni][q] = 0.f;

#pragma unroll
        for (int ks = 0; ks < 8; ++ks) {
            uint32_t A[3][2][4], B[3][2][4];
#pragma unroll
            for (int sp = 0; sp < 3; ++sp) {
#pragma unroll
                for (int mi = 0; mi < 2; ++mi) LDSM4(A[sp][mi], aAddr[sp][mi] + ks * 32);
#pragma unroll
                for (int g = 0; g < 2; ++g)   LDSM4(B[sp][g], bB + bOff[sp][g] + ks * 32);
            }
#pragma unroll
            for (int p = 0; p < 6; ++p) {
#pragma unroll
                for (int mi = 0; mi < 2; ++mi)
#pragma unroll
                    for (int ni = 0; ni < 4; ++ni) {
                        int g = ni >> 1, h = (ni & 1) * 2;
                        MMA16816(acc[mi][ni], A[PA[p]][mi], B[PB[p]][g][h], B[PB[p]][g][h + 1]);
                    }
            }
        }

        // epilogue: reference-rounded distance + running top-2
        int cb = c * CPC + wn * 32;
#pragma unroll
        for (int mi = 0; mi < 2; ++mi) {
#pragma unroll
            for (int ni = 0; ni < 4; ++ni) {
                int code = cb + ni * 8 + 2 * (l & 3);
                float re0 = sRE[code], re1 = sRE[code + 1];
                int s0 = mi * 2, s1 = mi * 2 + 1;
                float d;
                d = __fadd_rn(__fadd_rn(rxv[s0], re0), __fmul_rn(acc[mi][ni][0], -2.0f));
                ins2(d, code,     bestD[s0], bestI[s0], secD[s0], secI[s0]);
                d = __fadd_rn(__fadd_rn(rxv[s0], re1), __fmul_rn(acc[mi][ni][1], -2.0f));
                ins2(d, code + 1, bestD[s0], bestI[s0], secD[s0], secI[s0]);
                d = __fadd_rn(__fadd_rn(rxv[s1], re0), __fmul_rn(acc[mi][ni][2], -2.0f));
                ins2(d, code,     bestD[s1], bestI[s1], secD[s1], secI[s1]);
                d = __fadd_rn(__fadd_rn(rxv[s1], re1), __fmul_rn(acc[mi][ni][3], -2.0f));
                ins2(d, code + 1, bestD[s1], bestI[s1], secD[s1], secI[s1]);
            }
        }
        __syncthreads();                 // all readers done with buf (c&1)
        if (c + 2 < NCH) {
            uint32_t dst = smb + SM_B + (c & 1) * B_BUF;
            const char* src = (const char*)g_eTp + (size_t)(c + 2) * CPC * ROWB;
            for (int i = tid; i < B_BUF / 16; i += TPB) {
                int s = i / (B_SPLIT / 16), r = i - s * (B_SPLIT / 16);
                cp_async16(dst + i * 16, src + (size_t)s * ET_SPLIT + r * 16);
            }
            CP_COMMIT();
        }
    }

    // ---- top-2 merge across lanes (bfly over l&3) ----
#pragma unroll
    for (int s = 0; s < 4; ++s) {
#pragma unroll
        for (int m = 1; m <= 2; m <<= 1) {
            float obD = __shfl_xor_sync(0xffffffffu, bestD[s], m);
            int   obI = __shfl_xor_sync(0xffffffffu, bestI[s], m);
            float osD = __shfl_xor_sync(0xffffffffu, secD[s], m);
            int   osI = __shfl_xor_sync(0xffffffffu, secI[s], m);
            ins2(obD, obI, bestD[s], bestI[s], secD[s], secI[s]);
            ins2(osD, osI, bestD[s], bestI[s], secD[s], secI[s]);
        }
    }
    if ((l & 3) == 0) {
#pragma unroll
        for (int s = 0; s < 4; ++s) {
            int r = wm * 32 + (l >> 2) + s * 8;
            sRedD[(r * 2 + wn) * 2]     = bestD[s];
            sRedD[(r * 2 + wn) * 2 + 1] = secD[s];
            sRedI[(r * 2 + wn) * 2]     = bestI[s];
            sRedI[(r * 2 + wn) * 2 + 1] = secI[s];
        }
    }
    __syncthreads();

    // ---- per-row final: merge 2 warp halves, then EXACT fp32 recheck ----
    if (tid < RPB) {
        float bD = sRedD[tid * 4], sD = sRedD[tid * 4 + 1];
        int   bI = sRedI[tid * 4], sI = sRedI[tid * 4 + 1];
        ins2(sRedD[tid * 4 + 2], sRedI[tid * 4 + 2], bD, bI, sD, sI);
        ins2(sRedD[tid * 4 + 3], sRedI[tid * 4 + 3], bD, bI, sD, sI);

        // exact fp32 recompute of both candidates (reference rounding class)
        const float4* xr = (const float4*)(x + (row0 + tid) * DIMV);
        float rx = sRX[tid];
        int cand[2] = { bI, sI };
        float dex[2];
#pragma unroll
        for (int t = 0; t < 2; ++t) {
            const float4* er = (const float4*)(emb + (size_t)cand[t] * DIMV);
            float a0 = 0.f, a1 = 0.f, a2 = 0.f, a3 = 0.f;
#pragma unroll 8
            for (int j = 0; j < 32; ++j) {
                float4 xv = xr[j], ev = er[j];
                a0 = __fmaf_rn(xv.x, ev.x, a0);
                a1 = __fmaf_rn(xv.y, ev.y, a1);
                a2 = __fmaf_rn(xv.z, ev.z, a2);
                a3 = __fmaf_rn(xv.w, ev.w, a3);
            }
            float m = __fadd_rn(__fadd_rn(a0, a1), __fadd_rn(a2, a3));
            dex[t] = __fadd_rn(__fadd_rn(rx, sRE[cand[t]]), __fmul_rn(m, -2.0f));
        }
        int bi = lt(dex[1], cand[1], dex[0], cand[0]) ? cand[1] : cand[0];
        sBest[tid] = bi;
        atomicAdd(&g_counts[bi], 1);
    }
    __syncthreads();

    // ---- fused output: STE-rounded gather + fp64 loss partial ----
    double ls = 0.0;
    {
        const float4* xin4 = (const float4*)(x + row0 * DIMV);
        float4*       o4   = (float4*)(out + row0 * DIMV);
        const float4* e4   = (const float4*)emb;
        for (int i = tid; i < RPB * (DIMV / 4); i += TPB) {
            int rr  = i >> 5;
            int col = i & 31;
            float4 q  = e4[(size_t)sBest[rr] * 32 + col];
            float4 xv = xin4[i];
            float4 o;
            o.x = __fadd_rn(xv.x, __fadd_rn(q.x, -xv.x));
            o.y = __fadd_rn(xv.y, __fadd_rn(q.y, -xv.y));
            o.z = __fadd_rn(xv.z, __fadd_rn(q.z, -xv.z));
            o.w = __fadd_rn(xv.w, __fadd_rn(q.w, -xv.w));
            o4[i] = o;
            double dx = (double)q.x - xv.x, dy = (double)q.y - xv.y;
            double dz = (double)q.z - xv.z, dw = (double)q.w - xv.w;
            ls += dx * dx + dy * dy + dz * dz + dw * dw;
        }
    }
#pragma unroll
    for (int o = 16; o > 0; o >>= 1) ls += __shfl_down_sync(0xffffffffu, ls, o);
    if (l == 0) sLoss[wid] = ls;
    __syncthreads();
    if (tid == 0) {
        double t = 0.0;
#pragma unroll
        for (int i = 0; i < 8; ++i) t += sLoss[i];
        atomicAdd(&g_loss, t);
    }
}

// ---------------------------------------------------------------- finalize
__global__ void vq_finalize(float* __restrict__ out, int out_size) {
    __shared__ float red[8];
    int tid = threadIdx.x;  // 256
    float acc = 0.f;
    for (int k = tid; k < KCODES; k += 256) {
        float p = (float)g_counts[k] * (1.0f / (float)N_ROWS);
        acc += p * logf(p + 1e-10f);
    }
#pragma unroll
    for (int o = 16; o > 0; o >>= 1) acc += __shfl_down_sync(0xffffffffu, acc, o);
    if ((tid & 31) == 0) red[tid >> 5] = acc;
    __syncthreads();
    if (tid == 0) {
        float s = 0.f;
#pragma unroll
        for (int i = 0; i < 8; ++i) s += red[i];
        out[out_size - 2] = (float)(1.25 * (g_loss / (double)(N_ROWS * DIMV)));
        out[out_size - 1] = expf(-s);
    }
}

// ----------------------------------------------------------------
extern "C" void kernel_launch(void* const* d_in, const int* in_sizes, int n_in,
                              void* d_out, int out_size) {
    const float* x   = (const float*)d_in[0];
    const float* emb = (const float*)d_in[1];
    float*       out = (float*)d_out;
    (void)in_sizes; (void)n_in;

    cudaFuncSetAttribute(vq_main, cudaFuncAttributeMaxDynamicSharedMemorySize,
                         SMEM_TOTAL);

    vq_prep<<<8, 256>>>(emb);
    vq_main<<<NBLOCKS, TPB, SMEM_TOTAL>>>(x, emb, out);
    vq_finalize<<<1, 256>>>(out, out_size);
}

// round 8
// speedup vs baseline: 1.4135x; 1.1663x over previous
#include <cuda_runtime.h>
#include <cuda_bf16.h>
#include <cstdint>

// ---------------------------------------------------------------- constants
#define N_ROWS   65536
#define DIMV     128
#define KCODES   1024
#define RPB      128                  // rows per block (M)
#define CPC      64                   // codes per chunk (N)
#define NCH      (KCODES / CPC)       // 16
#define TPB      256
#define NBLOCKS  (N_ROWS / RPB)       // 512

// padded bf16 row: 136 elems = 272 B = 17 x 16B granules (conflict-free ldmatrix)
#define ROWB     272
#define XA_SPLIT (RPB * ROWB)         // 34816
#define B_SPLIT  (CPC * ROWB)         // 17408
#define B_BUF    (2 * B_SPLIT)        // 34816 (2 limbs)
#define ET_SPLIT (KCODES * ROWB)      // 278528

// smem layout
#define SM_XA    0
#define SM_B     (2 * XA_SPLIT)                   // 69632
#define SM_RE    (SM_B + 2 * B_BUF)               // 139264
#define SM_RX    (SM_RE + KCODES * 4)             // 143360
#define SM_REDD  (SM_RX + RPB * 4)                // 143872
#define SM_REDI  (SM_REDD + RPB * 4 * 4)          // 145920
#define SM_BEST  (SM_REDI + RPB * 4 * 4)          // 147968
#define SM_LOSS  (SM_BEST + RPB * 4)              // 148480
#define SMEM_TOTAL (SM_LOSS + 8 * 8)              // 148544

// ---------------------------------------------------------------- scratch
__device__ float  g_re[KCODES];
__device__ int    g_counts[KCODES];
__device__ double g_loss;
// padded bf16 codebook limbs: [2][1024][136] bf16
__device__ __align__(16) unsigned char g_eTp[2u * ET_SPLIT];

// ---------------------------------------------------------------- helpers
__device__ __forceinline__ uint32_t smem_u32(const void* p) {
    uint32_t a;
    asm("{ .reg .u64 t; cvta.to.shared.u64 t, %1; cvt.u32.u64 %0, t; }"
        : "=r"(a) : "l"(p));
    return a;
}
static __device__ __forceinline__ void cp_async16(uint32_t dst, const void* src) {
    asm volatile("cp.async.cg.shared.global [%0], [%1], 16;\n" :: "r"(dst), "l"(src));
}
#define CP_COMMIT() asm volatile("cp.async.commit_group;\n" ::: "memory")
#define CP_WAIT1()  asm volatile("cp.async.wait_group 1;\n" ::: "memory")

#define LDSM4(r, addr) \
    asm volatile("ldmatrix.sync.aligned.m8n8.x4.shared.b16 {%0,%1,%2,%3}, [%4];" \
        : "=r"((r)[0]), "=r"((r)[1]), "=r"((r)[2]), "=r"((r)[3]) : "r"(addr))

#define MMA16816(c, a, b0, b1) \
    asm volatile("mma.sync.aligned.m16n8k16.row.col.f32.bf16.bf16.f32 " \
        "{%0,%1,%2,%3}, {%4,%5,%6,%7}, {%8,%9}, {%0,%1,%2,%3};" \
        : "+f"((c)[0]), "+f"((c)[1]), "+f"((c)[2]), "+f"((c)[3]) \
        : "r"((a)[0]), "r"((a)[1]), "r"((a)[2]), "r"((a)[3]), "r"(b0), "r"(b1))

// ordering: (dA,iA) < (dB,iB)  [strict, lowest index on ties]
static __device__ __forceinline__ bool lt(float dA, int iA, float dB, int iB) {
    return dA < dB || (dA == dB && iA < iB);
}
// insert candidate into (best, sec) pair
static __device__ __forceinline__ void ins2(float d, int i,
                                            float& bD, int& bI, float& sD, int& sI) {
    if (lt(d, i, bD, bI)) { sD = bD; sI = bI; bD = d; bI = i; }
    else if (lt(d, i, sD, sI)) { sD = d; sI = i; }
}

// bf16 dual-limb sp of a scalar (x = limb0 + limb1 + O(2^-18 x))
static __device__ __forceinline__ __nv_bfloat16 split_bf(float f, int sp) {
    __nv_bfloat16 h1 = __float2bfloat16_rn(f);
    if (sp == 0) return h1;
    return __float2bfloat16_rn(__fadd_rn(f, -__bfloat162float(h1)));
}

// ---------------------------------------------------------------- prep
__global__ void vq_prep(const float* __restrict__ emb) {
    int g = blockIdx.x * blockDim.x + threadIdx.x;   // 0..2047
    int k = g >> 1, half = g & 1;
    const float4* e4 = (const float4*)(emb + (size_t)k * DIMV + half * 64);
    unsigned char* base = g_eTp + (size_t)k * ROWB + half * 128;
    double s = 0.0;
#pragma unroll
    for (int i = 0; i < 16; ++i) {
        float4 v = e4[i];
        s += (double)__fmul_rn(v.x, v.x) + (double)__fmul_rn(v.y, v.y)
           + (double)__fmul_rn(v.z, v.z) + (double)__fmul_rn(v.w, v.w);
#pragma unroll
        for (int sp = 0; sp < 2; ++sp) {
            unsigned char* p = base + (size_t)sp * ET_SPLIT + i * 8;
            *(__nv_bfloat162*)(p)     = __halves2bfloat162(split_bf(v.x, sp), split_bf(v.y, sp));
            *(__nv_bfloat162*)(p + 4) = __halves2bfloat162(split_bf(v.z, sp), split_bf(v.w, sp));
        }
    }
    s += __shfl_xor_sync(0xffffffffu, s, 1);
    if (!half) { g_re[k] = (float)s; g_counts[k] = 0; }
    if (g == 0) g_loss = 0.0;
}

// ---------------------------------------------------------------- main
__global__ __launch_bounds__(TPB, 1)
void vq_main(const float* __restrict__ x, const float* __restrict__ emb,
             float* __restrict__ out) {
    extern __shared__ __align__(16) char sm[];
    float*  sRE   = (float*)(sm + SM_RE);
    float*  sRX   = (float*)(sm + SM_RX);
    float*  sRedD = (float*)(sm + SM_REDD);
    int*    sRedI = (int*)  (sm + SM_REDI);
    int*    sBest = (int*)  (sm + SM_BEST);
    double* sLoss = (double*)(sm + SM_LOSS);

    const uint32_t smb = smem_u32(sm);
    const int tid = threadIdx.x, wid = tid >> 5, l = tid & 31;
    const int wm = wid & 3, wn = wid >> 2;          // 4 x 2 warp grid
    const size_t row0 = (size_t)blockIdx.x * RPB;

    // ---- stage x limbs (padded bf16) + fp64 row norms ----
    {
        int row = tid >> 1, half = tid & 1;
        const float4* xr = (const float4*)(x + (row0 + row) * DIMV + half * 64);
        char* base = sm + SM_XA + row * ROWB + half * 128;
        double s = 0.0;
#pragma unroll
        for (int i = 0; i < 16; ++i) {
            float4 v = xr[i];
            s += (double)__fmul_rn(v.x, v.x) + (double)__fmul_rn(v.y, v.y)
               + (double)__fmul_rn(v.z, v.z) + (double)__fmul_rn(v.w, v.w);
#pragma unroll
            for (int sp = 0; sp < 2; ++sp) {
                char* p = base + sp * XA_SPLIT + i * 8;
                *(__nv_bfloat162*)(p)     = __halves2bfloat162(split_bf(v.x, sp), split_bf(v.y, sp));
                *(__nv_bfloat162*)(p + 4) = __halves2bfloat162(split_bf(v.z, sp), split_bf(v.w, sp));
            }
        }
        s += __shfl_xor_sync(0xffffffffu, s, 1);
        if (!half) sRX[row] = (float)s;
    }
    for (int i = tid; i < KCODES; i += TPB) sRE[i] = g_re[i];

    // ---- prefetch B chunks 0,1 ----
    {
        const char* srcb = (const char*)g_eTp;
#pragma unroll
        for (int c = 0; c < 2; ++c) {
            uint32_t dst = smb + SM_B + c * B_BUF;
            const char* src = srcb + (size_t)c * CPC * ROWB;
            for (int i = tid; i < B_BUF / 16; i += TPB) {
                int s = i / (B_SPLIT / 16), r = i - s * (B_SPLIT / 16);
                cp_async16(dst + i * 16, src + (size_t)s * ET_SPLIT + r * 16);
            }
            CP_COMMIT();
        }
    }
    __syncthreads();   // staging of A/rx visible

    float rxv[4];
#pragma unroll
    for (int s = 0; s < 4; ++s) rxv[s] = sRX[wm * 32 + (l >> 2) + s * 8];

    uint32_t aAddr[2][2];
#pragma unroll
    for (int sp = 0; sp < 2; ++sp)
#pragma unroll
        for (int mi = 0; mi < 2; ++mi)
            aAddr[sp][mi] = smb + SM_XA + sp * XA_SPLIT
                          + (wm * 32 + mi * 16 + (l & 15)) * ROWB + ((l >> 4) & 1) * 16;
    uint32_t bOff[2][2];
#pragma unroll
    for (int sp = 0; sp < 2; ++sp)
#pragma unroll
        for (int g = 0; g < 2; ++g)
            bOff[sp][g] = sp * B_SPLIT
                        + (wn * 32 + g * 16 + (l & 7) + ((l >> 4) & 1) * 8) * ROWB
                        + ((l >> 3) & 1) * 16;

    float bestD[4], secD[4];
    int   bestI[4], secI[4];
#pragma unroll
    for (int s = 0; s < 4; ++s) {
        bestD[s] = secD[s] = 3.402823466e38f;
        bestI[s] = secI[s] = 0x7fffffff;
    }

    // 3 limb passes: (x1,e1), (x1,e2), (x2,e1)
    const int PA[3] = {0, 0, 1}, PB[3] = {0, 1, 0};

#pragma unroll 1
    for (int c = 0; c < NCH; ++c) {
        CP_WAIT1();
        __syncthreads();                 // buf (c&1) ready for all
        uint32_t bB = smb + SM_B + (c & 1) * B_BUF;

        float acc[2][4][4];
#pragma unroll
        for (int mi = 0; mi < 2; ++mi)
#pragma unroll
            for (int ni = 0; ni < 4; ++ni)
#pragma unroll
                for (int q = 0; q < 4; ++q) acc[mi][ni][q] = 0.f;

#pragma unroll
        for (int ks = 0; ks < 8; ++ks) {
            uint32_t A[2][2][4], B[2][2][4];
#pragma unroll
            for (int sp = 0; sp < 2; ++sp) {
#pragma unroll
                for (int mi = 0; mi < 2; ++mi) LDSM4(A[sp][mi], aAddr[sp][mi] + ks * 32);
#pragma unroll
                for (int g = 0; g < 2; ++g)   LDSM4(B[sp][g], bB + bOff[sp][g] + ks * 32);
            }
#pragma unroll
            for (int p = 0; p < 3; ++p) {
#pragma unroll
                for (int mi = 0; mi < 2; ++mi)
#pragma unroll
                    for (int ni = 0; ni < 4; ++ni) {
                        int g = ni >> 1, h = (ni & 1) * 2;
                        MMA16816(acc[mi][ni], A[PA[p]][mi], B[PB[p]][g][h], B[PB[p]][g][h + 1]);
                    }
            }
        }

        // epilogue: reference-rounded distance + running top-2
        int cb = c * CPC + wn * 32;
#pragma unroll
        for (int mi = 0; mi < 2; ++mi) {
#pragma unroll
            for (int ni = 0; ni < 4; ++ni) {
                int code = cb + ni * 8 + 2 * (l & 3);
                float re0 = sRE[code], re1 = sRE[code + 1];
                int s0 = mi * 2, s1 = mi * 2 + 1;
                float d;
                d = __fadd_rn(__fadd_rn(rxv[s0], re0), __fmul_rn(acc[mi][ni][0], -2.0f));
                ins2(d, code,     bestD[s0], bestI[s0], secD[s0], secI[s0]);
                d = __fadd_rn(__fadd_rn(rxv[s0], re1), __fmul_rn(acc[mi][ni][1], -2.0f));
                ins2(d, code + 1, bestD[s0], bestI[s0], secD[s0], secI[s0]);
                d = __fadd_rn(__fadd_rn(rxv[s1], re0), __fmul_rn(acc[mi][ni][2], -2.0f));
                ins2(d, code,     bestD[s1], bestI[s1], secD[s1], secI[s1]);
                d = __fadd_rn(__fadd_rn(rxv[s1], re1), __fmul_rn(acc[mi][ni][3], -2.0f));
                ins2(d, code + 1, bestD[s1], bestI[s1], secD[s1], secI[s1]);
            }
        }
        __syncthreads();                 // all readers done with buf (c&1)
        if (c + 2 < NCH) {
            uint32_t dst = smb + SM_B + (c & 1) * B_BUF;
            const char* src = (const char*)g_eTp + (size_t)(c + 2) * CPC * ROWB;
            for (int i = tid; i < B_BUF / 16; i += TPB) {
                int s = i / (B_SPLIT / 16), r = i - s * (B_SPLIT / 16);
                cp_async16(dst + i * 16, src + (size_t)s * ET_SPLIT + r * 16);
            }
            CP_COMMIT();
        }
    }

    // ---- top-2 merge across lanes (bfly over l&3) ----
#pragma unroll
    for (int s = 0; s < 4; ++s) {
#pragma unroll
        for (int m = 1; m <= 2; m <<= 1) {
            float obD = __shfl_xor_sync(0xffffffffu, bestD[s], m);
            int   obI = __shfl_xor_sync(0xffffffffu, bestI[s], m);
            float osD = __shfl_xor_sync(0xffffffffu, secD[s], m);
            int   osI = __shfl_xor_sync(0xffffffffu, secI[s], m);
            ins2(obD, obI, bestD[s], bestI[s], secD[s], secI[s]);
            ins2(osD, osI, bestD[s], bestI[s], secD[s], secI[s]);
        }
    }
    if ((l & 3) == 0) {
#pragma unroll
        for (int s = 0; s < 4; ++s) {
            int r = wm * 32 + (l >> 2) + s * 8;
            sRedD[(r * 2 + wn) * 2]     = bestD[s];
            sRedD[(r * 2 + wn) * 2 + 1] = secD[s];
            sRedI[(r * 2 + wn) * 2]     = bestI[s];
            sRedI[(r * 2 + wn) * 2 + 1] = secI[s];
        }
    }
    __syncthreads();

    // ---- per-row final: EXACT fp32 recheck of ALL 4 candidates ----
    if (tid < RPB) {
        const float4* xr = (const float4*)(x + (row0 + tid) * DIMV);
        float rx = sRX[tid];
        float bD = 3.402823466e38f;
        int   bi = 0x7fffffff;
#pragma unroll
        for (int t = 0; t < 4; ++t) {
            int cd = sRedI[tid * 4 + t];
            const float4* er = (const float4*)(emb + (size_t)cd * DIMV);
            float a0 = 0.f, a1 = 0.f, a2 = 0.f, a3 = 0.f;
#pragma unroll 8
            for (int j = 0; j < 32; ++j) {
                float4 xv = xr[j], ev = er[j];
                a0 = __fmaf_rn(xv.x, ev.x, a0);
                a1 = __fmaf_rn(xv.y, ev.y, a1);
                a2 = __fmaf_rn(xv.z, ev.z, a2);
                a3 = __fmaf_rn(xv.w, ev.w, a3);
            }
            float m = __fadd_rn(__fadd_rn(a0, a1), __fadd_rn(a2, a3));
            float d = __fadd_rn(__fadd_rn(rx, sRE[cd]), __fmul_rn(m, -2.0f));
            if (lt(d, cd, bD, bi)) { bD = d; bi = cd; }
        }
        sBest[tid] = bi;
        atomicAdd(&g_counts[bi], 1);
    }
    __syncthreads();

    // ---- fused output: STE-rounded gather + fp64 loss partial ----
    double ls = 0.0;
    {
        const float4* xin4 = (const float4*)(x + row0 * DIMV);
        float4*       o4   = (float4*)(out + row0 * DIMV);
        const float4* e4   = (const float4*)emb;
        for (int i = tid; i < RPB * (DIMV / 4); i += TPB) {
            int rr  = i >> 5;
            int col = i & 31;
            float4 q  = e4[(size_t)sBest[rr] * 32 + col];
            float4 xv = xin4[i];
            float4 o;
            o.x = __fadd_rn(xv.x, __fadd_rn(q.x, -xv.x));
            o.y = __fadd_rn(xv.y, __fadd_rn(q.y, -xv.y));
            o.z = __fadd_rn(xv.z, __fadd_rn(q.z, -xv.z));
            o.w = __fadd_rn(xv.w, __fadd_rn(q.w, -xv.w));
            o4[i] = o;
            double dx = (double)q.x - xv.x, dy = (double)q.y - xv.y;
            double dz = (double)q.z - xv.z, dw = (double)q.w - xv.w;
            ls += dx * dx + dy * dy + dz * dz + dw * dw;
        }
    }
#pragma unroll
    for (int o = 16; o > 0; o >>= 1) ls += __shfl_down_sync(0xffffffffu, ls, o);
    if (l == 0) sLoss[wid] = ls;
    __syncthreads();
    if (tid == 0) {
        double t = 0.0;
#pragma unroll
        for (int i = 0; i < 8; ++i) t += sLoss[i];
        atomicAdd(&g_loss, t);
    }
}

// ---------------------------------------------------------------- finalize
__global__ void vq_finalize(float* __restrict__ out, int out_size) {
    __shared__ float red[8];
    int tid = threadIdx.x;  // 256
    float acc = 0.f;
    for (int k = tid; k < KCODES; k += 256) {
        float p = (float)g_counts[k] * (1.0f / (float)N_ROWS);
        acc += p * logf(p + 1e-10f);
    }
#pragma unroll
    for (int o = 16; o > 0; o >>= 1) acc += __shfl_down_sync(0xffffffffu, acc, o);
    if ((tid & 31) == 0) red[tid >> 5] = acc;
    __syncthreads();
    if (tid == 0) {
        float s = 0.f;
#pragma unroll
        for (int i = 0; i < 8; ++i) s += red[i];
        out[out_size - 2] = (float)(1.25 * (g_loss / (double)(N_ROWS * DIMV)));
        out[out_size - 1] = expf(-s);
    }
}

// ----------------------------------------------------------------
extern "C" void kernel_launch(void* const* d_in, const int* in_sizes, int n_in,
                              void* d_out, int out_size) {
    const float* x   = (const float*)d_in[0];
    const float* emb = (const float*)d_in[1];
    float*       out = (float*)d_out;
    (void)in_sizes; (void)n_in;

    cudaFuncSetAttribute(vq_main, cudaFuncAttributeMaxDynamicSharedMemorySize,
                         SMEM_TOTAL);

    vq_prep<<<8, 256>>>(emb);
    vq_main<<<NBLOCKS, TPB, SMEM_TOTAL>>>(x, emb, out);
    vq_finalize<<<1, 256>>>(out, out_size);
}